// round 11
// baseline (speedup 1.0000x reference)
#include <cuda_runtime.h>
#include <cuda_fp16.h>

// Problem constants
#define SRC_HW   64
#define CELLS    4096        // 64*64 flow cells per batch-slice
#define CH       256
#define NB       4           // output batches
#define NN       4           // accumulated slices (num)
#define HO       192         // output H = W = 3*64
#define NBB      16          // NB*NN batch-slices
#define PW       72          // padded plane width/height (4 zero border each side)
#define RW       36          // half2 words per padded row
#define REPW     (PW * RW)   // half2 words per parity replica (2592)

// Precomputed per-(bb, cell) metadata:
//  .x = bitcast int: BYTE offset of patch-row base into the half2 replica pair
//       (parity*REPW + py*RW + (px>>1)) * 4
//  .y = m * (1 - ay)
//  .z = m * ay
//  .w = ax
__device__ float4 g_meta[NBB * CELLS];   // 1 MB static scratch

__global__ void meta_kernel(const float* __restrict__ flow,
                            const float* __restrict__ masks) {
    int idx = blockIdx.x * blockDim.x + threadIdx.x;
    if (idx >= NBB * CELLS) return;
    int bb   = idx >> 12;
    int cell = idx & (CELLS - 1);
    int cy = cell >> 6;
    int cx = cell & 63;

    float fy = flow[((size_t)(bb * 2 + 0)) * CELLS + cell];
    float fx = flow[((size_t)(bb * 2 + 1)) * CELLS + cell];
    float m  = masks[(size_t)bb * CELLS + cell];

    float by = (float)cy + fy;
    float bx = (float)cx + fx;
    float y0f = floorf(by);
    float x0f = floorf(bx);
    float ay = by - y0f;
    float ax = bx - x0f;
    int y0 = (int)y0f;
    int x0 = (int)x0f;

    int yb = min(max(y0 - 1, -4), SRC_HW);
    int xb = min(max(x0 - 1, -4), SRC_HW);
    int py = yb + 4;                  // 0..68
    int px = xb + 4;                  // 0..68
    int parity = px & 1;
    int word   = px >> 1;             // 0..34
    int mo = (parity * REPW + py * RW + word) * 4;   // byte offset

    g_meta[idx] = make_float4(__int_as_float(mo), m * (1.0f - ay), m * ay, ax);
}

static __device__ __forceinline__ unsigned pack_h2(float a, float b) {
    __half2 h = __floats2half2_rn(a, b);
    return *reinterpret_cast<unsigned*>(&h);
}

// One block per (channel, batch, cell-quarter). Source plane prefetched and
// converted to packed fp16 in registers (8 regs, not 16), written to BOTH
// x-parity replicas directly from registers (shfl supplies the straddling
// neighbor half). Patch rows are 2 LDS.32 from the parity-matched replica.
// 64-reg budget -> 4 CTAs/SM -> 32 warps to cover LDS latency.
__global__ __launch_bounds__(256, 4)
void extract_kernel(const float* __restrict__ src, float* __restrict__ out) {
    const int c = blockIdx.x;   // 0..255
    const int b = blockIdx.y;   // 0..3
    const int z = blockIdx.z;   // 0..3  (cell quarter)
    const int t = threadIdx.x;  // 0..255

    __shared__ __align__(16) unsigned rep[2 * REPW];   // 20736 B

    // Zero everything once (borders stay zero; interiors overwritten per n).
    {
        uint4 z4 = make_uint4(0u, 0u, 0u, 0u);
        uint4* rz = (uint4*)rep;
        for (int i = t; i < (2 * REPW) / 4; i += 256) rz[i] = z4;
    }

    float acc[4][9];
#pragma unroll
    for (int j = 0; j < 4; j++)
#pragma unroll
        for (int q = 0; q < 9; q++) acc[j][q] = 0.0f;

    const int cell0 = z * 1024;

    // Prefetch plane n=0, converting to packed fp16 immediately (8 regs).
    unsigned u[8];
    {
        const float4* sp = (const float4*)(src + ((size_t)(b * CH + c)) * CELLS);
#pragma unroll
        for (int k = 0; k < 4; k++) {
            float4 v = sp[t + 256 * k];
            u[2 * k]     = pack_h2(v.x, v.y);
            u[2 * k + 1] = pack_h2(v.z, v.w);
        }
    }

    for (int n = 0; n < NN; n++) {
        __syncthreads();   // previous gather (or zeroing) done before overwrite
        const int bb = n * NB + b;

        // Fill both replicas from registers.
        // Warp lanes cover consecutive float4s; each warp spans exactly 2
        // source rows, so the row-end lane (col4==15) has no in-row neighbor
        // and substitutes the zero border.
#pragma unroll
        for (int k = 0; k < 4; k++) {
            int i    = t + 256 * k;    // float4 index 0..1023
            int row  = i >> 4;         // 16 float4 per source row
            int col4 = i & 15;
            unsigned u0 = u[2 * k];
            unsigned u1 = u[2 * k + 1];
            unsigned nb = __shfl_down_sync(0xffffffffu, u0, 1);
            if (col4 == 15) nb = 0u;

            int base = (row + 4) * RW + 2 + 2 * col4;   // even -> 8B aligned
            *(uint2*)&rep[base] = make_uint2(u0, u1);
            unsigned w0 = (u0 >> 16) | (u1 << 16);      // (h1,h2)
            unsigned w1 = (u1 >> 16) | (nb << 16);      // (h3,next h0)
            *(uint2*)&rep[REPW + base] = make_uint2(w0, w1);
            if (col4 == 0)   // boundary word (border0, h0) at word index 1
                rep[REPW + (row + 4) * RW + 1] = (u0 & 0xFFFFu) << 16;
        }

        // Prefetch+convert next plane while this one is gathered.
        if (n < NN - 1) {
            const float4* sp = (const float4*)(src +
                ((size_t)(((n + 1) * NB + b) * CH + c)) * CELLS);
#pragma unroll
            for (int k = 0; k < 4; k++) {
                float4 v = sp[t + 256 * k];
                u[2 * k]     = pack_h2(v.x, v.y);
                u[2 * k + 1] = pack_h2(v.z, v.w);
            }
        }
        __syncthreads();

        const float4* __restrict__ metaB = g_meta + (size_t)bb * CELLS + cell0;

#pragma unroll
        for (int j = 0; j < 4; j++) {
            float4 mt = metaB[t + 256 * j];
            const __half2* __restrict__ p =
                (const __half2*)((const char*)rep + __float_as_int(mt.x));
            float wv0 = mt.y, wv1 = mt.z, ax = mt.w;

            // 4x4 patch: 2 LDS.32 per row
            float2 r0a = __half22float2(p[0]);
            float2 r0b = __half22float2(p[1]);
            float2 r1a = __half22float2(p[RW]);
            float2 r1b = __half22float2(p[RW + 1]);
            float2 r2a = __half22float2(p[2 * RW]);
            float2 r2b = __half22float2(p[2 * RW + 1]);
            float2 r3a = __half22float2(p[3 * RW]);
            float2 r3b = __half22float2(p[3 * RW + 1]);

            // Horizontal lerps (v0..v3 = a.x, a.y, b.x, b.y)
            float h0[3], h1[3], h2[3], h3[3];
            h0[0] = fmaf(ax, r0a.y - r0a.x, r0a.x);
            h0[1] = fmaf(ax, r0b.x - r0a.y, r0a.y);
            h0[2] = fmaf(ax, r0b.y - r0b.x, r0b.x);
            h1[0] = fmaf(ax, r1a.y - r1a.x, r1a.x);
            h1[1] = fmaf(ax, r1b.x - r1a.y, r1a.y);
            h1[2] = fmaf(ax, r1b.y - r1b.x, r1b.x);
            h2[0] = fmaf(ax, r2a.y - r2a.x, r2a.x);
            h2[1] = fmaf(ax, r2b.x - r2a.y, r2a.y);
            h2[2] = fmaf(ax, r2b.y - r2b.x, r2b.x);
            h3[0] = fmaf(ax, r3a.y - r3a.x, r3a.x);
            h3[1] = fmaf(ax, r3b.x - r3a.y, r3a.y);
            h3[2] = fmaf(ax, r3b.y - r3b.x, r3b.x);

            // Masked vertical FMAs
#pragma unroll
            for (int q = 0; q < 3; q++) {
                acc[j][0 + q] = fmaf(wv1, h1[q], fmaf(wv0, h0[q], acc[j][0 + q]));
                acc[j][3 + q] = fmaf(wv1, h2[q], fmaf(wv0, h1[q], acc[j][3 + q]));
                acc[j][6 + q] = fmaf(wv1, h3[q], fmaf(wv0, h2[q], acc[j][6 + q]));
            }
        }
    }

    // Write 4 cells x 3x3 outputs (adjacent threads -> adjacent 3-float groups)
    float* ob = out + ((size_t)(b * CH + c)) * (HO * HO);
#pragma unroll
    for (int j = 0; j < 4; j++) {
        int cell = cell0 + t + 256 * j;
        int cy = cell >> 6;
        int cx = cell & 63;
#pragma unroll
        for (int i = 0; i < 3; i++) {
            float* row = ob + (size_t)(cy * 3 + i) * HO + cx * 3;
            row[0] = acc[j][i * 3 + 0];
            row[1] = acc[j][i * 3 + 1];
            row[2] = acc[j][i * 3 + 2];
        }
    }
}

extern "C" void kernel_launch(void* const* d_in, const int* in_sizes, int n_in,
                              void* d_out, int out_size) {
    const float* src   = (const float*)d_in[0];  // (16, 256, 64, 64)
    const float* flow  = (const float*)d_in[1];  // (16, 2, 64, 64)
    const float* masks = (const float*)d_in[2];  // (16, 1, 64, 64)
    float* out = (float*)d_out;                  // (4, 256, 192, 192)

    meta_kernel<<<(NBB * CELLS + 255) / 256, 256>>>(flow, masks);

    dim3 grid(CH, NB, 4);
    extract_kernel<<<grid, 256>>>(src, out);
}

// round 12
// speedup vs baseline: 1.1470x; 1.1470x over previous
#include <cuda_runtime.h>
#include <cuda_fp16.h>

// Problem constants
#define SRC_HW   64
#define CELLS    4096        // 64*64 flow cells per batch-slice
#define CH       256
#define NB       4           // output batches
#define NN       4           // accumulated slices (num)
#define HO       192         // output H = W = 3*64
#define NBB      16          // NB*NN batch-slices
#define PW       72          // padded plane width/height (4 zero border each side)
#define RW       36          // half2 words per padded row
#define REPW     (PW * RW)   // half2 words per parity replica (2592)
#define BUFW     (2 * REPW)  // words per double-buffer slot (both parities)

// Precomputed per-(bb, cell) metadata:
//  .x = bitcast int: BYTE offset of patch-row base into the half2 replica pair
//       (parity*REPW + py*RW + (px>>1)) * 4
//  .y = m * (1 - ay)
//  .z = m * ay
//  .w = ax
__device__ float4 g_meta[NBB * CELLS];   // 1 MB static scratch

__global__ void meta_kernel(const float* __restrict__ flow,
                            const float* __restrict__ masks) {
    int idx = blockIdx.x * blockDim.x + threadIdx.x;
    if (idx >= NBB * CELLS) return;
    int bb   = idx >> 12;
    int cell = idx & (CELLS - 1);
    int cy = cell >> 6;
    int cx = cell & 63;

    float fy = flow[((size_t)(bb * 2 + 0)) * CELLS + cell];
    float fx = flow[((size_t)(bb * 2 + 1)) * CELLS + cell];
    float m  = masks[(size_t)bb * CELLS + cell];

    float by = (float)cy + fy;
    float bx = (float)cx + fx;
    float y0f = floorf(by);
    float x0f = floorf(bx);
    float ay = by - y0f;
    float ax = bx - x0f;
    int y0 = (int)y0f;
    int x0 = (int)x0f;

    int yb = min(max(y0 - 1, -4), SRC_HW);
    int xb = min(max(x0 - 1, -4), SRC_HW);
    int py = yb + 4;                  // 0..68
    int px = xb + 4;                  // 0..68
    int parity = px & 1;
    int word   = px >> 1;             // 0..34
    int mo = (parity * REPW + py * RW + word) * 4;   // byte offset

    g_meta[idx] = make_float4(__int_as_float(mo), m * (1.0f - ay), m * ay, ax);
}

static __device__ __forceinline__ unsigned pack_h2(float a, float b) {
    __half2 h = __floats2half2_rn(a, b);
    return *reinterpret_cast<unsigned*>(&h);
}

// One block per (channel, batch, cell-quarter). Double-buffered SMEM replica
// pairs: gather reads buf[n&1] while the register-side fill writes
// buf[(n+1)&1] — one barrier per plane instead of two, fill overlaps gather.
// Patch rows are 2 LDS.32 from the parity-matched replica.
__global__ __launch_bounds__(256, 3)
void extract_kernel(const float* __restrict__ src, float* __restrict__ out) {
    const int c = blockIdx.x;   // 0..255
    const int b = blockIdx.y;   // 0..3
    const int z = blockIdx.z;   // 0..3  (cell quarter)
    const int t = threadIdx.x;  // 0..255

    __shared__ __align__(16) unsigned rep[2 * BUFW];   // 41472 B

    // Zero both buffers once (borders stay zero; interiors overwritten).
    {
        uint4 z4 = make_uint4(0u, 0u, 0u, 0u);
        uint4* rz = (uint4*)rep;
        for (int i = t; i < (2 * BUFW) / 4; i += 256) rz[i] = z4;
    }

    float acc[4][9];
#pragma unroll
    for (int j = 0; j < 4; j++)
#pragma unroll
        for (int q = 0; q < 9; q++) acc[j][q] = 0.0f;

    const int cell0 = z * 1024;

    // Fill helper data: warp lanes cover consecutive float4s; each warp spans
    // exactly 2 source rows, so the row-end lane (col4==15) has no in-row
    // neighbor and substitutes the zero border.
    unsigned u[8];

    // Prefetch + convert plane n=0
    {
        const float4* sp = (const float4*)(src + ((size_t)(b * CH + c)) * CELLS);
#pragma unroll
        for (int k = 0; k < 4; k++) {
            float4 v = sp[t + 256 * k];
            u[2 * k]     = pack_h2(v.x, v.y);
            u[2 * k + 1] = pack_h2(v.z, v.w);
        }
    }
    __syncthreads();   // zeroing done before first fill

    // Fill buf0 with plane 0
#pragma unroll
    for (int k = 0; k < 4; k++) {
        int i    = t + 256 * k;
        int row  = i >> 4;
        int col4 = i & 15;
        unsigned u0 = u[2 * k];
        unsigned u1 = u[2 * k + 1];
        unsigned nb = __shfl_down_sync(0xffffffffu, u0, 1);
        if (col4 == 15) nb = 0u;
        int base = (row + 4) * RW + 2 + 2 * col4;
        *(uint2*)&rep[base] = make_uint2(u0, u1);
        *(uint2*)&rep[REPW + base] =
            make_uint2((u0 >> 16) | (u1 << 16), (u1 >> 16) | (nb << 16));
        if (col4 == 0)
            rep[REPW + (row + 4) * RW + 1] = (u0 & 0xFFFFu) << 16;
    }

    // Prefetch + convert plane n=1
    {
        const float4* sp = (const float4*)(src +
            ((size_t)((NB + b) * CH + c)) * CELLS);
#pragma unroll
        for (int k = 0; k < 4; k++) {
            float4 v = sp[t + 256 * k];
            u[2 * k]     = pack_h2(v.x, v.y);
            u[2 * k + 1] = pack_h2(v.z, v.w);
        }
    }

    for (int n = 0; n < NN; n++) {
        __syncthreads();   // fill of buf[n&1] complete across CTA
        const int bb = n * NB + b;
        const unsigned* __restrict__ buf = rep + (n & 1) * BUFW;

        const float4* __restrict__ metaB = g_meta + (size_t)bb * CELLS + cell0;

#pragma unroll
        for (int j = 0; j < 4; j++) {
            float4 mt = metaB[t + 256 * j];
            const __half2* __restrict__ p =
                (const __half2*)((const char*)buf + __float_as_int(mt.x));
            float wv0 = mt.y, wv1 = mt.z, ax = mt.w;

            // 4x4 patch: 2 LDS.32 per row
            float2 r0a = __half22float2(p[0]);
            float2 r0b = __half22float2(p[1]);
            float2 r1a = __half22float2(p[RW]);
            float2 r1b = __half22float2(p[RW + 1]);
            float2 r2a = __half22float2(p[2 * RW]);
            float2 r2b = __half22float2(p[2 * RW + 1]);
            float2 r3a = __half22float2(p[3 * RW]);
            float2 r3b = __half22float2(p[3 * RW + 1]);

            // Horizontal lerps (v0..v3 = a.x, a.y, b.x, b.y)
            float h0[3], h1[3], h2[3], h3[3];
            h0[0] = fmaf(ax, r0a.y - r0a.x, r0a.x);
            h0[1] = fmaf(ax, r0b.x - r0a.y, r0a.y);
            h0[2] = fmaf(ax, r0b.y - r0b.x, r0b.x);
            h1[0] = fmaf(ax, r1a.y - r1a.x, r1a.x);
            h1[1] = fmaf(ax, r1b.x - r1a.y, r1a.y);
            h1[2] = fmaf(ax, r1b.y - r1b.x, r1b.x);
            h2[0] = fmaf(ax, r2a.y - r2a.x, r2a.x);
            h2[1] = fmaf(ax, r2b.x - r2a.y, r2a.y);
            h2[2] = fmaf(ax, r2b.y - r2b.x, r2b.x);
            h3[0] = fmaf(ax, r3a.y - r3a.x, r3a.x);
            h3[1] = fmaf(ax, r3b.x - r3a.y, r3a.y);
            h3[2] = fmaf(ax, r3b.y - r3b.x, r3b.x);

            // Masked vertical FMAs
#pragma unroll
            for (int q = 0; q < 3; q++) {
                acc[j][0 + q] = fmaf(wv1, h1[q], fmaf(wv0, h0[q], acc[j][0 + q]));
                acc[j][3 + q] = fmaf(wv1, h2[q], fmaf(wv0, h1[q], acc[j][3 + q]));
                acc[j][6 + q] = fmaf(wv1, h3[q], fmaf(wv0, h2[q], acc[j][6 + q]));
            }
        }

        // Fill the other buffer with plane n+1 (registers already hold it),
        // then prefetch plane n+2. Safe: all warps passed the sync above, so
        // no one is still gathering buf[(n+1)&1] (that was iteration n-1).
        if (n < NN - 1) {
            unsigned* nxt = rep + ((n + 1) & 1) * BUFW;
#pragma unroll
            for (int k = 0; k < 4; k++) {
                int i    = t + 256 * k;
                int row  = i >> 4;
                int col4 = i & 15;
                unsigned u0 = u[2 * k];
                unsigned u1 = u[2 * k + 1];
                unsigned nb = __shfl_down_sync(0xffffffffu, u0, 1);
                if (col4 == 15) nb = 0u;
                int base = (row + 4) * RW + 2 + 2 * col4;
                *(uint2*)&nxt[base] = make_uint2(u0, u1);
                *(uint2*)&nxt[REPW + base] =
                    make_uint2((u0 >> 16) | (u1 << 16), (u1 >> 16) | (nb << 16));
                if (col4 == 0)
                    nxt[REPW + (row + 4) * RW + 1] = (u0 & 0xFFFFu) << 16;
            }
            if (n < NN - 2) {
                const float4* sp = (const float4*)(src +
                    ((size_t)(((n + 2) * NB + b) * CH + c)) * CELLS);
#pragma unroll
                for (int k = 0; k < 4; k++) {
                    float4 v = sp[t + 256 * k];
                    u[2 * k]     = pack_h2(v.x, v.y);
                    u[2 * k + 1] = pack_h2(v.z, v.w);
                }
            }
        }
    }

    // Write 4 cells x 3x3 outputs (adjacent threads -> adjacent 3-float groups)
    float* ob = out + ((size_t)(b * CH + c)) * (HO * HO);
#pragma unroll
    for (int j = 0; j < 4; j++) {
        int cell = cell0 + t + 256 * j;
        int cy = cell >> 6;
        int cx = cell & 63;
#pragma unroll
        for (int i = 0; i < 3; i++) {
            float* row = ob + (size_t)(cy * 3 + i) * HO + cx * 3;
            row[0] = acc[j][i * 3 + 0];
            row[1] = acc[j][i * 3 + 1];
            row[2] = acc[j][i * 3 + 2];
        }
    }
}

extern "C" void kernel_launch(void* const* d_in, const int* in_sizes, int n_in,
                              void* d_out, int out_size) {
    const float* src   = (const float*)d_in[0];  // (16, 256, 64, 64)
    const float* flow  = (const float*)d_in[1];  // (16, 2, 64, 64)
    const float* masks = (const float*)d_in[2];  // (16, 1, 64, 64)
    float* out = (float*)d_out;                  // (4, 256, 192, 192)

    meta_kernel<<<(NBB * CELLS + 255) / 256, 256>>>(flow, masks);

    dim3 grid(CH, NB, 4);
    extract_kernel<<<grid, 256>>>(src, out);
}